// round 5
// baseline (speedup 1.0000x reference)
#include <cuda_runtime.h>
#include <cuda_bf16.h>
#include <math.h>

// Problem constants (fixed-shape problem: N=2,000,000, P=64, C=100)
#define CLS 100
#define FEAT 64
#define BLOCK 256
#define WARPS 8          // warps per block, each with a private smem s-buffer
#define UNROLL 8         // rows per warp per iteration (MLP)
#define MAIN_GRID 152    // GB300 has 152 SMs; 1 block/SM (smem-limited)

// Global scratch (allocation-free rule: __device__ globals)
__device__ float g_s[CLS * FEAT];   // per-class per-feature sums
__device__ float g_A;               // sum of ||x_row||^2 / (n_c - 1)
__device__ int   g_cnt[CLS];        // class counts
__device__ int   g_is64;            // 1 if t is int64, 0 if int32

// ---------------------------------------------------------------------------
// Kernel 0: sniff t dtype. Values are in [0,100); if int64, every high 32-bit
// word is 0. 64 random int32 values all being 0 has prob ~1e-128.
// ---------------------------------------------------------------------------
__global__ void sniff_kernel(const int* __restrict__ t_words) {
    if (threadIdx.x == 0 && blockIdx.x == 0) {
        int z = 1;
        #pragma unroll
        for (int i = 0; i < 64; i++) z &= (t_words[2 * i + 1] == 0);
        g_is64 = z;
    }
}

// ---------------------------------------------------------------------------
// Kernel 1: zero scratch
// ---------------------------------------------------------------------------
__global__ void zero_kernel() {
    int i = blockIdx.x * blockDim.x + threadIdx.x;
    int stride = gridDim.x * blockDim.x;
    for (int j = i; j < CLS * FEAT; j += stride) g_s[j] = 0.0f;
    if (i < CLS) g_cnt[i] = 0;
    if (i == 0) g_A = 0.0f;
}

// ---------------------------------------------------------------------------
// Kernel 2: class histogram over t (16 MB read). Shared histogram per block,
// then ~100 global atomics per block.
// ---------------------------------------------------------------------------
__global__ void hist_kernel(const void* __restrict__ t_raw, int n) {
    __shared__ int h[CLS];
    for (int i = threadIdx.x; i < CLS; i += blockDim.x) h[i] = 0;
    __syncthreads();
    const int is64 = g_is64;
    int i0 = blockIdx.x * blockDim.x + threadIdx.x;
    int stride = gridDim.x * blockDim.x;
    if (is64) {
        const long long* t = (const long long*)t_raw;
        for (int i = i0; i < n; i += stride) atomicAdd(&h[(int)t[i]], 1);
    } else {
        const int* t = (const int*)t_raw;
        for (int i = i0; i < n; i += stride) atomicAdd(&h[t[i]], 1);
    }
    __syncthreads();
    for (int i = threadIdx.x; i < CLS; i += blockDim.x)
        if (h[i]) atomicAdd(&g_cnt[i], h[i]);
}

// ---------------------------------------------------------------------------
// Kernel 3: main pass over x (512 MB). One warp processes one row per step
// (32 lanes x float2 = 64 features -> conflict-free lane-disjoint smem RMW
// into the warp's PRIVATE buffer; no atomics). Per-lane register accumulates
// ||x||^2 * 1/(n_c-1).
// ---------------------------------------------------------------------------
__global__ __launch_bounds__(BLOCK, 1)
void main_kernel(const float2* __restrict__ xv, const void* __restrict__ t_raw,
                 int nRows) {
    extern __shared__ float smem[];
    // layout: [WARPS][CLS*FEAT] warp-private sum buffers, then w[CLS]
    const int lane = threadIdx.x & 31;
    const int warp = threadIdx.x >> 5;
    float* wbuf = smem + warp * (CLS * FEAT);
    float* wcls = smem + WARPS * (CLS * FEAT);

    for (int i = threadIdx.x; i < WARPS * CLS * FEAT; i += BLOCK) smem[i] = 0.0f;
    for (int i = threadIdx.x; i < CLS; i += BLOCK)
        wcls[i] = 1.0f / ((float)g_cnt[i] - 1.0f);
    __syncthreads();

    const int is64 = g_is64;
    const long long* t64 = (const long long*)t_raw;
    const int* t32 = (const int*)t_raw;

    const int totalWarps = gridDim.x * WARPS;
    const int gw = blockIdx.x * WARPS + warp;
    float acc = 0.0f;

    for (int r0 = gw * UNROLL; r0 < nRows; r0 += totalWarps * UNROLL) {
        float2 v[UNROLL];
        int c[UNROLL];
        #pragma unroll
        for (int i = 0; i < UNROLL; i++) {
            int r = r0 + i;
            if (r < nRows) {
                c[i] = is64 ? (int)t64[r] : t32[r];
                v[i] = xv[(size_t)r * 32 + lane];
            } else {
                c[i] = -1;
                v[i] = make_float2(0.0f, 0.0f);
            }
        }
        #pragma unroll
        for (int i = 0; i < UNROLL; i++) {
            if (c[i] >= 0) {
                float w = wcls[c[i]];
                float* p = wbuf + c[i] * FEAT + lane * 2;
                float2 s = *(float2*)p;
                s.x += v[i].x;
                s.y += v[i].y;
                *(float2*)p = s;
                acc = fmaf(fmaf(v[i].x, v[i].x, v[i].y * v[i].y), w, acc);
            }
        }
    }

    // warp-reduce acc, one global atomic per warp
    #pragma unroll
    for (int o = 16; o; o >>= 1) acc += __shfl_xor_sync(0xffffffffu, acc, o);
    if (lane == 0) atomicAdd(&g_A, acc);
    __syncthreads();

    // reduce the WARPS private copies -> global s
    for (int i = threadIdx.x; i < CLS * FEAT; i += BLOCK) {
        float s = 0.0f;
        #pragma unroll
        for (int wcp = 0; wcp < WARPS; wcp++) s += smem[wcp * (CLS * FEAT) + i];
        atomicAdd(&g_s[i], s);
    }
}

// ---------------------------------------------------------------------------
// Kernel 4: finalize. result = (A - sum_c sum_p s^2/(n(n-1))) / CLS
// ---------------------------------------------------------------------------
__global__ void finalize_kernel(float* __restrict__ out) {
    __shared__ float red[256];
    float b = 0.0f;
    for (int i = threadIdx.x; i < CLS * FEAT; i += 256) {
        int c = i / FEAT;
        float n = (float)g_cnt[c];
        float s = g_s[i];
        b += s * s / (n * (n - 1.0f));
    }
    red[threadIdx.x] = b;
    __syncthreads();
    for (int st = 128; st; st >>= 1) {
        if (threadIdx.x < st) red[threadIdx.x] += red[threadIdx.x + st];
        __syncthreads();
    }
    if (threadIdx.x == 0) out[0] = (g_A - red[0]) / (float)CLS;
}

// ---------------------------------------------------------------------------
extern "C" void kernel_launch(void* const* d_in, const int* in_sizes, int n_in,
                              void* d_out, int out_size) {
    const float2* x = (const float2*)d_in[0];
    const void* t = d_in[1];
    int nRows = in_sizes[0] / FEAT;

    const int smem_bytes = (WARPS * CLS * FEAT + CLS) * (int)sizeof(float);
    cudaFuncSetAttribute(main_kernel,
                         cudaFuncAttributeMaxDynamicSharedMemorySize,
                         smem_bytes);

    sniff_kernel<<<1, 32>>>((const int*)t);
    zero_kernel<<<(CLS * FEAT + 255) / 256, 256>>>();
    hist_kernel<<<2048, 256>>>(t, nRows);
    main_kernel<<<MAIN_GRID, BLOCK, smem_bytes>>>(x, t, nRows);
    finalize_kernel<<<1, 256>>>((float*)d_out);
}

// round 14
// speedup vs baseline: 1.2595x; 1.2595x over previous
#include <cuda_runtime.h>
#include <cuda_bf16.h>
#include <math.h>

// Problem constants (fixed-shape problem: N=2,000,000, P=64, C=100)
#define CLS 100
#define FEAT 64
#define HFEAT 32         // features per warp (half a row, 1 float per lane)
#define BLOCK 512
#define WARPS 16         // warps per block, each with a private smem s-buffer
#define UNROLL 16        // rows per warp-stream per iteration (MLP)
#define MAIN_GRID 152    // GB300 has 152 SMs; 1 block/SM (smem-limited)

// Global scratch (allocation-free rule: __device__ globals)
__device__ float g_s[CLS * FEAT];   // per-class per-feature sums
__device__ float g_A;               // sum of ||x_row||^2 / (n_c - 1)
__device__ int   g_cnt[CLS];        // class counts
__device__ int   g_is64;            // 1 if t is int64, 0 if int32

// ---------------------------------------------------------------------------
// Kernel 0: sniff t dtype. Values are in [0,100); if int64, every high 32-bit
// word is 0. 64 random int32 values all being 0 has prob ~1e-128.
// ---------------------------------------------------------------------------
__global__ void sniff_kernel(const int* __restrict__ t_words) {
    if (threadIdx.x == 0 && blockIdx.x == 0) {
        int z = 1;
        #pragma unroll
        for (int i = 0; i < 64; i++) z &= (t_words[2 * i + 1] == 0);
        g_is64 = z;
    }
}

// ---------------------------------------------------------------------------
// Kernel 1: zero scratch
// ---------------------------------------------------------------------------
__global__ void zero_kernel() {
    int i = blockIdx.x * blockDim.x + threadIdx.x;
    int stride = gridDim.x * blockDim.x;
    for (int j = i; j < CLS * FEAT; j += stride) g_s[j] = 0.0f;
    if (i < CLS) g_cnt[i] = 0;
    if (i == 0) g_A = 0.0f;
}

// ---------------------------------------------------------------------------
// Kernel 2: class histogram over t (16 MB read). Shared histogram per block,
// then ~100 global atomics per block.
// ---------------------------------------------------------------------------
__global__ void hist_kernel(const void* __restrict__ t_raw, int n) {
    __shared__ int h[CLS];
    for (int i = threadIdx.x; i < CLS; i += blockDim.x) h[i] = 0;
    __syncthreads();
    const int is64 = g_is64;
    int i0 = blockIdx.x * blockDim.x + threadIdx.x;
    int stride = gridDim.x * blockDim.x;
    if (is64) {
        const long long* t = (const long long*)t_raw;
        for (int i = i0; i < n; i += stride) atomicAdd(&h[(int)t[i]], 1);
    } else {
        const int* t = (const int*)t_raw;
        for (int i = i0; i < n; i += stride) atomicAdd(&h[t[i]], 1);
    }
    __syncthreads();
    for (int i = threadIdx.x; i < CLS; i += blockDim.x)
        if (h[i]) atomicAdd(&g_cnt[i], h[i]);
}

// ---------------------------------------------------------------------------
// Kernel 3: main pass over x (512 MB). A PAIR of warps covers one row stream:
// warp with (warp&1)==h handles features [h*32, h*32+32). Each warp has a
// PRIVATE CLS x 32 float smem buffer -> lane-disjoint non-atomic RMW, no
// conflicts. 16 warps/SM (2x the previous version) at the same smem footprint.
// Per-lane register accumulates partial ||x||^2 * 1/(n_c-1).
// ---------------------------------------------------------------------------
__global__ __launch_bounds__(BLOCK, 1)
void main_kernel(const float* __restrict__ x, const void* __restrict__ t_raw,
                 int nRows) {
    extern __shared__ float smem[];
    // layout: [WARPS][CLS*HFEAT] warp-private sum buffers, then wcls[CLS]
    const int lane = threadIdx.x & 31;
    const int warp = threadIdx.x >> 5;
    const int half = warp & 1;
    float* wbuf = smem + warp * (CLS * HFEAT);
    float* wcls = smem + WARPS * (CLS * HFEAT);

    for (int i = threadIdx.x; i < WARPS * CLS * HFEAT; i += BLOCK) smem[i] = 0.0f;
    for (int i = threadIdx.x; i < CLS; i += BLOCK)
        wcls[i] = 1.0f / ((float)g_cnt[i] - 1.0f);
    __syncthreads();

    const int is64 = g_is64;
    const long long* t64 = (const long long*)t_raw;
    const int* t32 = (const int*)t_raw;

    // column this lane reads within each row
    const int col = half * HFEAT + lane;
    const int totalStreams = (gridDim.x * WARPS) >> 1;
    const int stream = (blockIdx.x * WARPS + warp) >> 1;
    float acc = 0.0f;

    for (int r0 = stream * UNROLL; r0 < nRows; r0 += totalStreams * UNROLL) {
        float v[UNROLL];
        int c[UNROLL];
        #pragma unroll
        for (int i = 0; i < UNROLL; i++) {
            int r = r0 + i;
            if (r < nRows) {
                c[i] = is64 ? (int)t64[r] : t32[r];
                v[i] = x[(size_t)r * FEAT + col];
            } else {
                c[i] = -1;
                v[i] = 0.0f;
            }
        }
        #pragma unroll
        for (int i = 0; i < UNROLL; i++) {
            if (c[i] >= 0) {
                float w = wcls[c[i]];
                float* p = wbuf + c[i] * HFEAT + lane;
                *p += v[i];
                acc = fmaf(v[i] * v[i], w, acc);
            }
        }
    }

    // warp-reduce acc, one global atomic per warp
    #pragma unroll
    for (int o = 16; o; o >>= 1) acc += __shfl_xor_sync(0xffffffffu, acc, o);
    if (lane == 0) atomicAdd(&g_A, acc);
    __syncthreads();

    // reduce the WARPS private copies -> global s.
    // global slot i maps to (class, feat); warps with (warp&1)==feat/32 hold it.
    for (int i = threadIdx.x; i < CLS * FEAT; i += BLOCK) {
        int cls = i / FEAT;
        int f = i % FEAT;
        int h = f / HFEAT;
        int fi = f % HFEAT;
        float s = 0.0f;
        #pragma unroll
        for (int wp = 0; wp < WARPS / 2; wp++)
            s += smem[(2 * wp + h) * (CLS * HFEAT) + cls * HFEAT + fi];
        atomicAdd(&g_s[i], s);
    }
}

// ---------------------------------------------------------------------------
// Kernel 4: finalize. result = (A - sum_c sum_p s^2/(n(n-1))) / CLS
// ---------------------------------------------------------------------------
__global__ void finalize_kernel(float* __restrict__ out) {
    __shared__ float red[256];
    float b = 0.0f;
    for (int i = threadIdx.x; i < CLS * FEAT; i += 256) {
        int c = i / FEAT;
        float n = (float)g_cnt[c];
        float s = g_s[i];
        b += s * s / (n * (n - 1.0f));
    }
    red[threadIdx.x] = b;
    __syncthreads();
    for (int st = 128; st; st >>= 1) {
        if (threadIdx.x < st) red[threadIdx.x] += red[threadIdx.x + st];
        __syncthreads();
    }
    if (threadIdx.x == 0) out[0] = (g_A - red[0]) / (float)CLS;
}

// ---------------------------------------------------------------------------
extern "C" void kernel_launch(void* const* d_in, const int* in_sizes, int n_in,
                              void* d_out, int out_size) {
    const float* x = (const float*)d_in[0];
    const void* t = d_in[1];
    int nRows = in_sizes[0] / FEAT;

    const int smem_bytes = (WARPS * CLS * HFEAT + CLS) * (int)sizeof(float);
    cudaFuncSetAttribute(main_kernel,
                         cudaFuncAttributeMaxDynamicSharedMemorySize,
                         smem_bytes);

    sniff_kernel<<<1, 32>>>((const int*)t);
    zero_kernel<<<(CLS * FEAT + 255) / 256, 256>>>();
    hist_kernel<<<2048, 256>>>(t, nRows);
    main_kernel<<<MAIN_GRID, BLOCK, smem_bytes>>>(x, t, nRows);
    finalize_kernel<<<1, 256>>>((float*)d_out);
}

// round 16
// speedup vs baseline: 1.6593x; 1.3174x over previous
#include <cuda_runtime.h>
#include <cuda_bf16.h>
#include <math.h>

// Problem constants (fixed-shape problem: N=2,000,000, P=64, C=100)
#define CLS 100
#define FEAT 64
#define HFEAT 32         // features per warp (half a row, 1 float per lane)
#define BLOCK 512
#define WARPS 16         // warps per block, each with a private smem s-buffer
#define UNROLL 32        // rows per warp-stream per iteration (MLP)
#define MAIN_GRID 152    // GB300 has 152 SMs; 1 block/SM (smem-limited)

// Global scratch (allocation-free rule: __device__ globals)
__device__ float g_s[CLS * FEAT];   // per-class per-feature sums
__device__ float g_A;               // sum of ||x_row||^2 / (n_c - 1)
__device__ int   g_cnt[CLS];        // class counts
__device__ int   g_is64;            // 1 if t is int64, 0 if int32
__device__ int   g_done;            // completion counter for fused finalize

// ---------------------------------------------------------------------------
// Kernel 1: zero scratch + sniff t dtype (fused). Values in [0,100); if int64,
// every high 32-bit word is 0. 64 random int32 all zero has prob ~1e-128.
// ---------------------------------------------------------------------------
__global__ void zero_kernel(const int* __restrict__ t_words) {
    int i = blockIdx.x * blockDim.x + threadIdx.x;
    int stride = gridDim.x * blockDim.x;
    for (int j = i; j < CLS * FEAT; j += stride) g_s[j] = 0.0f;
    if (i < CLS) g_cnt[i] = 0;
    if (i == 0) {
        g_A = 0.0f;
        g_done = 0;
        int z = 1;
        #pragma unroll
        for (int k = 0; k < 64; k++) z &= (t_words[2 * k + 1] == 0);
        g_is64 = z;
    }
}

// ---------------------------------------------------------------------------
// Kernel 2: class histogram over t (16 MB read). Shared histogram per block,
// then ~100 global atomics per block.
// ---------------------------------------------------------------------------
__global__ void hist_kernel(const void* __restrict__ t_raw, int n) {
    __shared__ int h[CLS];
    for (int i = threadIdx.x; i < CLS; i += blockDim.x) h[i] = 0;
    __syncthreads();
    const int is64 = g_is64;
    int i0 = blockIdx.x * blockDim.x + threadIdx.x;
    int stride = gridDim.x * blockDim.x;
    if (is64) {
        const long long* t = (const long long*)t_raw;
        for (int i = i0; i < n; i += stride) atomicAdd(&h[(int)t[i]], 1);
    } else {
        const int* t = (const int*)t_raw;
        for (int i = i0; i < n; i += stride) atomicAdd(&h[t[i]], 1);
    }
    __syncthreads();
    for (int i = threadIdx.x; i < CLS; i += blockDim.x)
        if (h[i]) atomicAdd(&g_cnt[i], h[i]);
}

// ---------------------------------------------------------------------------
// Kernel 3: main pass over x (512 MB) + fused finalize (last block).
// A PAIR of warps covers one row stream: warp with (warp&1)==h handles
// features [h*32, h*32+32). Each warp has a PRIVATE CLS x 32 float smem
// buffer -> lane-disjoint non-atomic RMW, no conflicts. UNROLL=32 with
// hoisted bounds check for MLP. Per-lane register accumulates
// ||x||^2 * 1/(n_c-1).
// ---------------------------------------------------------------------------
__global__ __launch_bounds__(BLOCK, 1)
void main_kernel(const float* __restrict__ x, const void* __restrict__ t_raw,
                 int nRows, float* __restrict__ out) {
    extern __shared__ float smem[];
    __shared__ int isLast;
    // layout: [WARPS][CLS*HFEAT] warp-private sum buffers, then wcls[CLS]
    const int lane = threadIdx.x & 31;
    const int warp = threadIdx.x >> 5;
    const int half = warp & 1;
    float* wbuf = smem + warp * (CLS * HFEAT);
    float* wcls = smem + WARPS * (CLS * HFEAT);

    for (int i = threadIdx.x; i < WARPS * CLS * HFEAT; i += BLOCK) smem[i] = 0.0f;
    for (int i = threadIdx.x; i < CLS; i += BLOCK)
        wcls[i] = 1.0f / ((float)g_cnt[i] - 1.0f);
    __syncthreads();

    const int is64 = g_is64;
    const long long* t64 = (const long long*)t_raw;
    const int* t32 = (const int*)t_raw;

    // column this lane reads within each row
    const int col = half * HFEAT + lane;
    const int totalStreams = (gridDim.x * WARPS) >> 1;
    const int stream = (blockIdx.x * WARPS + warp) >> 1;
    float acc = 0.0f;

    for (int r0 = stream * UNROLL; r0 < nRows; r0 += totalStreams * UNROLL) {
        if (r0 + UNROLL <= nRows) {
            // Full batch: no per-row bounds checks; all loads batched for MLP.
            float v[UNROLL];
            int c[UNROLL];
            const float* xp = x + (size_t)r0 * FEAT + col;
            #pragma unroll
            for (int i = 0; i < UNROLL; i++) {
                c[i] = is64 ? (int)t64[r0 + i] : t32[r0 + i];
                v[i] = xp[i * FEAT];
            }
            #pragma unroll
            for (int i = 0; i < UNROLL; i++) {
                float w = wcls[c[i]];
                float* p = wbuf + c[i] * HFEAT + lane;
                *p += v[i];
                acc = fmaf(v[i] * v[i], w, acc);
            }
        } else {
            // Tail batch: scalar path with bounds checks.
            for (int i = 0; i < UNROLL; i++) {
                int r = r0 + i;
                if (r < nRows) {
                    int cc = is64 ? (int)t64[r] : t32[r];
                    float vv = x[(size_t)r * FEAT + col];
                    float w = wcls[cc];
                    float* p = wbuf + cc * HFEAT + lane;
                    *p += vv;
                    acc = fmaf(vv * vv, w, acc);
                }
            }
        }
    }

    // warp-reduce acc, one global atomic per warp
    #pragma unroll
    for (int o = 16; o; o >>= 1) acc += __shfl_xor_sync(0xffffffffu, acc, o);
    if (lane == 0) atomicAdd(&g_A, acc);
    __syncthreads();

    // reduce the WARPS private copies -> global s.
    // global slot i maps to (class, feat); warps with (warp&1)==feat/32 hold it.
    for (int i = threadIdx.x; i < CLS * FEAT; i += BLOCK) {
        int cls = i / FEAT;
        int f = i % FEAT;
        int h = f / HFEAT;
        int fi = f % HFEAT;
        float s = 0.0f;
        #pragma unroll
        for (int wp = 0; wp < WARPS / 2; wp++)
            s += smem[(2 * wp + h) * (CLS * HFEAT) + cls * HFEAT + fi];
        atomicAdd(&g_s[i], s);
    }

    // ---- fused finalize: last block computes the scalar output ----
    __threadfence();
    __syncthreads();
    if (threadIdx.x == 0)
        isLast = (atomicAdd(&g_done, 1) == (int)gridDim.x - 1);
    __syncthreads();
    if (isLast) {
        __threadfence();  // acquire: all other blocks' g_s/g_A adds visible
        float* red = smem;  // wbuf no longer needed
        float b = 0.0f;
        for (int i = threadIdx.x; i < CLS * FEAT; i += BLOCK) {
            int c = i / FEAT;
            float n = (float)g_cnt[c];
            float s = g_s[i];
            b += s * s / (n * (n - 1.0f));
        }
        red[threadIdx.x] = b;
        __syncthreads();
        for (int st = BLOCK / 2; st; st >>= 1) {
            if (threadIdx.x < st) red[threadIdx.x] += red[threadIdx.x + st];
            __syncthreads();
        }
        if (threadIdx.x == 0) out[0] = (g_A - red[0]) / (float)CLS;
    }
}

// ---------------------------------------------------------------------------
extern "C" void kernel_launch(void* const* d_in, const int* in_sizes, int n_in,
                              void* d_out, int out_size) {
    const float* x = (const float*)d_in[0];
    const void* t = d_in[1];
    int nRows = in_sizes[0] / FEAT;

    const int smem_bytes = (WARPS * CLS * HFEAT + CLS) * (int)sizeof(float);
    cudaFuncSetAttribute(main_kernel,
                         cudaFuncAttributeMaxDynamicSharedMemorySize,
                         smem_bytes);

    zero_kernel<<<(CLS * FEAT + 255) / 256, 256>>>((const int*)t);
    hist_kernel<<<2048, 256>>>(t, nRows);
    main_kernel<<<MAIN_GRID, BLOCK, smem_bytes>>>(x, t, nRows, (float*)d_out);
}